// round 10
// baseline (speedup 1.0000x reference)
#include <cuda_runtime.h>

// fm: (1, 256, 256, 256) fp32 NHWC; rois: (2000, 5) int32 [b, x, y, w, h]; pool = 7.
#define FM_W 256
#define FM_C 256
#define POOLSZ 7
#define NCELL (POOLSZ * POOLSZ)
#define RPB 4                 // spatially-binned ROIs per block
#define NBUCKET 256           // 16x16 spatial tiles of 16px

__device__ int g_perm[4096];  // spatially-sorted roi order

// ---- Kernel A: bin ROIs by 16px spatial tile of their center ----
// Single block; histogram -> scan -> scatter. Order within a bucket is
// nondeterministic (atomics) but each ROI writes only its own output slot,
// so the final output is unaffected.
__global__ void bin_rois_kernel(const int* __restrict__ rois, int n)
{
    __shared__ int hist[NBUCKET];
    __shared__ int cur[NBUCKET];
    int tid = threadIdx.x;  // 256

    hist[tid] = 0;
    __syncthreads();

    for (int i = tid; i < n; i += 256) {
        int x = rois[i * 5 + 1], y = rois[i * 5 + 2];
        int w = rois[i * 5 + 3], h = rois[i * 5 + 4];
        int cx = (x + (w >> 1)) >> 4;      // 0..15
        int cy = (y + (h >> 1)) >> 4;
        atomicAdd(&hist[cy * 16 + cx], 1);
    }
    __syncthreads();

    if (tid == 0) {                        // serial exclusive scan (256 entries)
        int acc = 0;
        for (int b = 0; b < NBUCKET; b++) { int c = hist[b]; cur[b] = acc; acc += c; }
    }
    __syncthreads();

    for (int i = tid; i < n; i += 256) {
        int x = rois[i * 5 + 1], y = rois[i * 5 + 2];
        int w = rois[i * 5 + 3], h = rois[i * 5 + 4];
        int cx = (x + (w >> 1)) >> 4;
        int cy = (y + (h >> 1)) >> 4;
        int pos = atomicAdd(&cur[cy * 16 + cx], 1);
        g_perm[pos] = i;
    }
}

// ---- Kernel B: main pooling; each block does RPB spatially-adjacent ROIs ----
__global__ __launch_bounds__(256) void roi_pool_kernel(
    const float* __restrict__ fm,      // [H, W, C]
    const int* __restrict__ rois,      // [N, 5]
    float* __restrict__ out,           // [N, 7, 7, C]
    int n_rois)
{
    int tid = threadIdx.x;

    __shared__ int4   sIdx[NCELL];   // 16B-aligned corner base indices (float4 units)
    __shared__ float4 sWt[NCELL];    // fused bilinear weights

    int c  = tid & 63;        // channel float4 index 0..63
    int ty = tid >> 6;        // cell-group 0..3

    const float4* f4 = (const float4*)fm;

    for (int r = 0; r < RPB; r++) {
        int slot = blockIdx.x * RPB + r;
        if (slot >= n_rois) break;
        int roi = g_perm[slot];

        // Build the per-cell fused table: 49 threads, both axes inline.
        if (tid < NCELL) {
            int rx = rois[roi * 5 + 1];
            int ry = rois[roi * 5 + 2];
            int rw = rois[roi * 5 + 3];
            int rh = rois[roi * 5 + 4];

            int py = tid / POOLSZ;
            int px = tid - py * POOLSZ;

            float lh = (float)rh;
            float fyc = ((float)py + 0.5f) * (lh / (float)POOLSZ) - 0.5f;
            fyc = fminf(fmaxf(fyc, 0.0f), lh - 1.0f);
            int iy0 = (int)floorf(fyc);
            int iy1 = min(iy0 + 1, rh - 1);
            float fy = fyc - (float)iy0;

            float lw = (float)rw;
            float fxc = ((float)px + 0.5f) * (lw / (float)POOLSZ) - 0.5f;
            fxc = fminf(fmaxf(fxc, 0.0f), lw - 1.0f);
            int ix0 = (int)floorf(fxc);
            int ix1 = min(ix0 + 1, rw - 1);
            float fx = fxc - (float)ix0;

            int y0 = ry + iy0, y1 = ry + iy1;
            int x0 = rx + ix0, x1 = rx + ix1;

            int4 idx;
            idx.x = (y0 * FM_W + x0) * (FM_C / 4);
            idx.y = (y0 * FM_W + x1) * (FM_C / 4);
            idx.z = (y1 * FM_W + x0) * (FM_C / 4);
            idx.w = (y1 * FM_W + x1) * (FM_C / 4);
            sIdx[tid] = idx;

            float ofx = 1.0f - fx, ofy = 1.0f - fy;
            float4 w;
            w.x = ofx * ofy;
            w.y = fx  * ofy;
            w.z = ofx * fy;
            w.w = fx  * fy;
            sWt[tid] = w;
        }
        __syncthreads();

        float4* o4 = (float4*)out + (size_t)roi * NCELL * (FM_C / 4);

        #pragma unroll 4
        for (int cell = ty; cell < NCELL; cell += 4) {
            int4   idx = sIdx[cell];    // broadcast LDS.128
            float4 w   = sWt[cell];     // broadcast LDS.128

            const float4 g00 = __ldg(f4 + idx.x + c);
            const float4 g01 = __ldg(f4 + idx.y + c);
            const float4 g10 = __ldg(f4 + idx.z + c);
            const float4 g11 = __ldg(f4 + idx.w + c);

            float4 rr;
            rr.x = g00.x * w.x + g01.x * w.y + g10.x * w.z + g11.x * w.w;
            rr.y = g00.y * w.x + g01.y * w.y + g10.y * w.z + g11.y * w.w;
            rr.z = g00.z * w.x + g01.z * w.y + g10.z * w.z + g11.z * w.w;
            rr.w = g00.w * w.x + g01.w * w.y + g10.w * w.z + g11.w * w.w;

            // Streaming store: output written once, never read — evict first.
            __stcs(&o4[cell * (FM_C / 4) + c], rr);
        }
        __syncthreads();   // before next ROI overwrites the tables
    }
}

extern "C" void kernel_launch(void* const* d_in, const int* in_sizes, int n_in,
                              void* d_out, int out_size)
{
    const float* fm  = (const float*)d_in[0];
    const int* rois  = (const int*)d_in[1];
    float* out       = (float*)d_out;

    int n_rois = in_sizes[1] / 5;

    bin_rois_kernel<<<1, 256>>>(rois, n_rois);
    int grid = (n_rois + RPB - 1) / RPB;
    roi_pool_kernel<<<grid, 256>>>(fm, rois, out, n_rois);
}

// round 12
// speedup vs baseline: 1.0316x; 1.0316x over previous
#include <cuda_runtime.h>
#include <cuda_fp16.h>

// fm: (1, 256, 256, 256) fp32 NHWC; rois: (2000, 5) int32 [b, x, y, w, h]; pool = 7.
#define FM_W 256
#define FM_C 256
#define POOLSZ 7
#define NCELL (POOLSZ * POOLSZ)
#define FM_ELEMS (256 * 256 * 256)

// 32MB fp16 shadow of the feature map (static scratch; no allocation).
__device__ __align__(16) __half g_fmh[FM_ELEMS];

__device__ __forceinline__ unsigned h2_bits(__half2 h) {
    union { __half2 h; unsigned u; } cvt;
    cvt.h = h;
    return cvt.u;
}

// ---- Kernel A: fp32 -> fp16 convert, pure streaming. 8 floats/thread. ----
__global__ __launch_bounds__(256) void convert_kernel(const float4* __restrict__ fm4)
{
    int i = blockIdx.x * blockDim.x + threadIdx.x;   // 0 .. FM_ELEMS/8-1
    float4 a = __ldg(&fm4[2 * i]);
    float4 b = __ldg(&fm4[2 * i + 1]);
    uint4 packed;
    packed.x = h2_bits(__float22half2_rn(make_float2(a.x, a.y)));
    packed.y = h2_bits(__float22half2_rn(make_float2(a.z, a.w)));
    packed.z = h2_bits(__float22half2_rn(make_float2(b.x, b.y)));
    packed.w = h2_bits(__float22half2_rn(make_float2(b.z, b.w)));
    ((uint4*)g_fmh)[i] = packed;
}

// ---- Kernel B: ROI pooling reading the fp16 copy ----
__global__ __launch_bounds__(256) void roi_pool_kernel(
    const int* __restrict__ rois,      // [N, 5]
    float* __restrict__ out)           // [N, 7, 7, C] fp32
{
    int roi = blockIdx.x;
    int tid = threadIdx.x;

    __shared__ int   sx0[POOLSZ], sx1[POOLSZ], sy0[POOLSZ], sy1[POOLSZ];
    __shared__ float sfx[POOLSZ], sfy[POOLSZ];
    __shared__ int4   sIdx[NCELL];   // pixel index of the 4 corner pixels
    __shared__ float4 sWt[NCELL];    // fused bilinear weights w00,w01,w10,w11

    if (tid < 2 * POOLSZ) {
        int  p   = (tid >= POOLSZ) ? tid - POOLSZ : tid;
        bool isx = tid < POOLSZ;
        int start = rois[roi * 5 + (isx ? 1 : 2)];
        int len   = rois[roi * 5 + (isx ? 3 : 4)];
        float lf = (float)len;
        float f = ((float)p + 0.5f) * (lf / (float)POOLSZ) - 0.5f;
        f = fminf(fmaxf(f, 0.0f), lf - 1.0f);
        int i0 = (int)floorf(f);
        int i1 = min(i0 + 1, len - 1);
        float fr = f - (float)i0;
        if (isx) { sx0[p] = start + i0; sx1[p] = start + i1; sfx[p] = fr; }
        else     { sy0[p] = start + i0; sy1[p] = start + i1; sfy[p] = fr; }
    }
    __syncthreads();

    if (tid < NCELL) {
        int py = tid / POOLSZ;
        int px = tid - py * POOLSZ;
        int y0 = sy0[py], y1 = sy1[py];
        int x0 = sx0[px], x1 = sx1[px];
        float fy = sfy[py], fx = sfx[px];
        float ofx = 1.0f - fx, ofy = 1.0f - fy;
        int4 idx;                         // pixel index (scaled by 256 ch later)
        idx.x = y0 * FM_W + x0;
        idx.y = y0 * FM_W + x1;
        idx.z = y1 * FM_W + x0;
        idx.w = y1 * FM_W + x1;
        sIdx[tid] = idx;
        float4 w;
        w.x = ofx * ofy;
        w.y = fx  * ofy;
        w.z = ofx * fy;
        w.w = fx  * fy;
        sWt[tid] = w;
    }
    __syncthreads();

    int lane8 = (tid & 31) * 8;   // channel offset (8 halves = 16B per thread)
    int ty    = tid >> 5;         // cell-group 0..7

    const __half* fmh = g_fmh;
    float* obase = out + (size_t)roi * NCELL * FM_C + lane8;

    for (int cell = ty; cell < NCELL; cell += 8) {
        int4   idx = sIdx[cell];    // broadcast LDS.128
        float4 w   = sWt[cell];     // broadcast LDS.128

        const uint4 u00 = __ldg((const uint4*)(fmh + idx.x * FM_C + lane8));
        const uint4 u01 = __ldg((const uint4*)(fmh + idx.y * FM_C + lane8));
        const uint4 u10 = __ldg((const uint4*)(fmh + idx.z * FM_C + lane8));
        const uint4 u11 = __ldg((const uint4*)(fmh + idx.w * FM_C + lane8));

        // Unpack 8 halves per corner and blend in fp32.
        float4 r0, r1;   // channels 0-3 and 4-7
        {
            float2 a0 = __half22float2(*(const __half2*)&u00.x);
            float2 b0 = __half22float2(*(const __half2*)&u01.x);
            float2 c0 = __half22float2(*(const __half2*)&u10.x);
            float2 d0 = __half22float2(*(const __half2*)&u11.x);
            r0.x = a0.x * w.x + b0.x * w.y + c0.x * w.z + d0.x * w.w;
            r0.y = a0.y * w.x + b0.y * w.y + c0.y * w.z + d0.y * w.w;
            float2 a1 = __half22float2(*(const __half2*)&u00.y);
            float2 b1 = __half22float2(*(const __half2*)&u01.y);
            float2 c1 = __half22float2(*(const __half2*)&u10.y);
            float2 d1 = __half22float2(*(const __half2*)&u11.y);
            r0.z = a1.x * w.x + b1.x * w.y + c1.x * w.z + d1.x * w.w;
            r0.w = a1.y * w.x + b1.y * w.y + c1.y * w.z + d1.y * w.w;
            float2 a2 = __half22float2(*(const __half2*)&u00.z);
            float2 b2 = __half22float2(*(const __half2*)&u01.z);
            float2 c2 = __half22float2(*(const __half2*)&u10.z);
            float2 d2 = __half22float2(*(const __half2*)&u11.z);
            r1.x = a2.x * w.x + b2.x * w.y + c2.x * w.z + d2.x * w.w;
            r1.y = a2.y * w.x + b2.y * w.y + c2.y * w.z + d2.y * w.w;
            float2 a3 = __half22float2(*(const __half2*)&u00.w);
            float2 b3 = __half22float2(*(const __half2*)&u01.w);
            float2 c3 = __half22float2(*(const __half2*)&u10.w);
            float2 d3 = __half22float2(*(const __half2*)&u11.w);
            r1.z = a3.x * w.x + b3.x * w.y + c3.x * w.z + d3.x * w.w;
            r1.w = a3.y * w.x + b3.y * w.y + c3.y * w.z + d3.y * w.w;
        }

        // Streaming stores: output written once, never read — evict first so
        // the fp32 fm + fp16 copy stay L2-resident across graph replays.
        float* o = obase + cell * FM_C;
        __stcs((float4*)o, r0);
        __stcs((float4*)(o + 4), r1);
    }
}

extern "C" void kernel_launch(void* const* d_in, const int* in_sizes, int n_in,
                              void* d_out, int out_size)
{
    const float* fm  = (const float*)d_in[0];
    const int* rois  = (const int*)d_in[1];
    float* out       = (float*)d_out;

    int n_rois = in_sizes[1] / 5;

    convert_kernel<<<FM_ELEMS / 8 / 256, 256>>>((const float4*)fm);
    roi_pool_kernel<<<n_rois, 256>>>(rois, out);
}

// round 13
// speedup vs baseline: 1.1251x; 1.0907x over previous
#include <cuda_runtime.h>

// fm: (1, 256, 256, 256) fp32 NHWC; rois: (2000, 5) int32 [b, x, y, w, h]; pool = 7.
#define FM_W 256
#define FM_C 256
#define POOLSZ 7
#define NCELL (POOLSZ * POOLSZ)

struct F8 { float4 a, b; };

// 256-bit load (sm_103a native). All addresses here are 32B-aligned:
// fm base (cudaMalloc) + pixel*1024B + lane*32B.
__device__ __forceinline__ F8 ldg256(const float* p) {
    F8 v;
    asm("ld.global.nc.v8.f32 {%0,%1,%2,%3,%4,%5,%6,%7}, [%8];"
        : "=f"(v.a.x), "=f"(v.a.y), "=f"(v.a.z), "=f"(v.a.w),
          "=f"(v.b.x), "=f"(v.b.y), "=f"(v.b.z), "=f"(v.b.w)
        : "l"(p));
    return v;
}

__global__ __launch_bounds__(256) void roi_pool_kernel(
    const float* __restrict__ fm,      // [H, W, C]
    const int* __restrict__ rois,      // [N, 5]
    float* __restrict__ out)           // [N, 7, 7, C]
{
    int roi = blockIdx.x;
    int tid = threadIdx.x;

    __shared__ int   sx0[POOLSZ], sx1[POOLSZ], sy0[POOLSZ], sy1[POOLSZ];
    __shared__ float sfx[POOLSZ], sfy[POOLSZ];
    __shared__ int4   sIdx[NCELL];   // 16B-aligned: float-unit corner base indices
    __shared__ float4 sWt[NCELL];    // fused bilinear weights w00,w01,w10,w11

    if (tid < 2 * POOLSZ) {
        int  p   = (tid >= POOLSZ) ? tid - POOLSZ : tid;
        bool isx = tid < POOLSZ;
        int start = rois[roi * 5 + (isx ? 1 : 2)];
        int len   = rois[roi * 5 + (isx ? 3 : 4)];
        float lf = (float)len;
        float f = ((float)p + 0.5f) * (lf / (float)POOLSZ) - 0.5f;
        f = fminf(fmaxf(f, 0.0f), lf - 1.0f);
        int i0 = (int)floorf(f);
        int i1 = min(i0 + 1, len - 1);
        float fr = f - (float)i0;
        if (isx) { sx0[p] = start + i0; sx1[p] = start + i1; sfx[p] = fr; }
        else     { sy0[p] = start + i0; sy1[p] = start + i1; sfy[p] = fr; }
    }
    __syncthreads();

    if (tid < NCELL) {
        int py = tid / POOLSZ;
        int px = tid - py * POOLSZ;
        int y0 = sy0[py], y1 = sy1[py];
        int x0 = sx0[px], x1 = sx1[px];
        float fy = sfy[py], fx = sfx[px];
        float ofx = 1.0f - fx, ofy = 1.0f - fy;
        int4 idx;                               // float-unit pixel base
        idx.x = (y0 * FM_W + x0) * FM_C;
        idx.y = (y0 * FM_W + x1) * FM_C;
        idx.z = (y1 * FM_W + x0) * FM_C;
        idx.w = (y1 * FM_W + x1) * FM_C;
        sIdx[tid] = idx;
        float4 w;
        w.x = ofx * ofy;
        w.y = fx  * ofy;
        w.z = ofx * fy;
        w.w = fx  * fy;
        sWt[tid] = w;
    }
    __syncthreads();

    int lane = (tid & 31) * 8;   // float offset within pixel (32B per thread)
    int ty   = tid >> 5;         // cell-group 0..7

    float* obase = out + (size_t)roi * NCELL * FM_C + lane;

    for (int cell = ty; cell < NCELL; cell += 8) {
        int4   idx = sIdx[cell];    // broadcast LDS.128
        float4 w   = sWt[cell];     // broadcast LDS.128

        F8 g00 = ldg256(fm + idx.x + lane);
        F8 g01 = ldg256(fm + idx.y + lane);
        F8 g10 = ldg256(fm + idx.z + lane);
        F8 g11 = ldg256(fm + idx.w + lane);

        float4 r0, r1;
        r0.x = g00.a.x * w.x + g01.a.x * w.y + g10.a.x * w.z + g11.a.x * w.w;
        r0.y = g00.a.y * w.x + g01.a.y * w.y + g10.a.y * w.z + g11.a.y * w.w;
        r0.z = g00.a.z * w.x + g01.a.z * w.y + g10.a.z * w.z + g11.a.z * w.w;
        r0.w = g00.a.w * w.x + g01.a.w * w.y + g10.a.w * w.z + g11.a.w * w.w;
        r1.x = g00.b.x * w.x + g01.b.x * w.y + g10.b.x * w.z + g11.b.x * w.w;
        r1.y = g00.b.y * w.x + g01.b.y * w.y + g10.b.y * w.z + g11.b.y * w.w;
        r1.z = g00.b.z * w.x + g01.b.z * w.y + g10.b.z * w.z + g11.b.z * w.w;
        r1.w = g00.b.w * w.x + g01.b.w * w.y + g10.b.w * w.z + g11.b.w * w.w;

        // Streaming store: output written once, never read — evict first.
        float* o = obase + cell * FM_C;
        __stcs((float4*)o, r0);
        __stcs((float4*)(o + 4), r1);
    }
}

extern "C" void kernel_launch(void* const* d_in, const int* in_sizes, int n_in,
                              void* d_out, int out_size)
{
    const float* fm  = (const float*)d_in[0];
    const int* rois  = (const int*)d_in[1];
    float* out       = (float*)d_out;

    int n_rois = in_sizes[1] / 5;

    roi_pool_kernel<<<n_rois, 256>>>(fm, rois, out);
}

// round 14
// speedup vs baseline: 1.2065x; 1.0723x over previous
#include <cuda_runtime.h>
#include <cstdint>

// fm: (1, 256, 256, 256) fp32 NHWC; rois: (2000, 5) int32 [b, x, y, w, h]; pool = 7.
#define FM_W 256
#define FM_C 256
#define POOLSZ 7
#define NCELL 49
#define DEPTH 4

__device__ __forceinline__ uint32_t s2u(const void* p) {
    uint32_t a;
    asm("{ .reg .u64 t; cvta.to.shared.u64 t, %1; cvt.u32.u64 %0, t; }"
        : "=r"(a) : "l"(p));
    return a;
}

__device__ __forceinline__ void mbar_init(uint32_t mbar, uint32_t cnt) {
    asm volatile("mbarrier.init.shared.b64 [%0], %1;" :: "r"(mbar), "r"(cnt) : "memory");
}
__device__ __forceinline__ void mbar_expect_tx(uint32_t mbar, uint32_t bytes) {
    asm volatile("mbarrier.arrive.expect_tx.shared.b64 _, [%0], %1;"
                 :: "r"(mbar), "r"(bytes) : "memory");
}
__device__ __forceinline__ void bulk_ld(uint32_t dst, const void* src, uint32_t bytes,
                                        uint32_t mbar) {
    asm volatile("cp.async.bulk.shared::cta.global.mbarrier::complete_tx::bytes "
                 "[%0], [%1], %2, [%3];"
                 :: "r"(dst), "l"(src), "r"(bytes), "r"(mbar) : "memory");
}
__device__ __forceinline__ void mbar_wait(uint32_t mbar, uint32_t parity) {
    asm volatile(
        "{\n\t"
        ".reg .pred P;\n\t"
        "WAIT_%=:\n\t"
        "mbarrier.try_wait.parity.acquire.cta.shared::cta.b64 P, [%0], %1, 0x989680;\n\t"
        "@P bra.uni DONE_%=;\n\t"
        "bra.uni WAIT_%=;\n\t"
        "DONE_%=:\n\t"
        "}" :: "r"(mbar), "r"(parity) : "memory");
}

__global__ __launch_bounds__(256) void roi_pool_kernel(
    const float* __restrict__ fm,      // [H, W, C]
    const int* __restrict__ rois,      // [N, 5]
    float* __restrict__ out)           // [N, 7, 7, C]
{
    int roi = blockIdx.x;
    int tid = threadIdx.x;

    __shared__ __align__(16) float bufs[DEPTH][4 * FM_C];  // 4 corners x 1KB
    __shared__ __align__(8)  uint64_t mbar[DEPTH];
    __shared__ int   sx0[POOLSZ], sx1[POOLSZ], sy0[POOLSZ], sy1[POOLSZ];
    __shared__ float sfx[POOLSZ], sfy[POOLSZ];
    __shared__ int4   sIdx[NCELL];   // float-unit pixel base of the 4 corners
    __shared__ float4 sWt[NCELL];    // fused bilinear weights

    if (tid < 2 * POOLSZ) {
        int  p   = (tid >= POOLSZ) ? tid - POOLSZ : tid;
        bool isx = tid < POOLSZ;
        int start = rois[roi * 5 + (isx ? 1 : 2)];
        int len   = rois[roi * 5 + (isx ? 3 : 4)];
        float lf = (float)len;
        float f = ((float)p + 0.5f) * (lf / (float)POOLSZ) - 0.5f;
        f = fminf(fmaxf(f, 0.0f), lf - 1.0f);
        int i0 = (int)floorf(f);
        int i1 = min(i0 + 1, len - 1);
        float fr = f - (float)i0;
        if (isx) { sx0[p] = start + i0; sx1[p] = start + i1; sfx[p] = fr; }
        else     { sy0[p] = start + i0; sy1[p] = start + i1; sfy[p] = fr; }
    }
    if (tid == 0) {
        #pragma unroll
        for (int k = 0; k < DEPTH; k++) mbar_init(s2u(&mbar[k]), 1);
    }
    __syncthreads();

    if (tid < NCELL) {
        int py = tid / POOLSZ;
        int px = tid - py * POOLSZ;
        int y0 = sy0[py], y1 = sy1[py];
        int x0 = sx0[px], x1 = sx1[px];
        float fy = sfy[py], fx = sfx[px];
        float ofx = 1.0f - fx, ofy = 1.0f - fy;
        int4 idx;
        idx.x = (y0 * FM_W + x0) * FM_C;
        idx.y = (y0 * FM_W + x1) * FM_C;
        idx.z = (y1 * FM_W + x0) * FM_C;
        idx.w = (y1 * FM_W + x1) * FM_C;
        sIdx[tid] = idx;
        float4 w;
        w.x = ofx * ofy;
        w.y = fx  * ofy;
        w.z = ofx * fy;
        w.w = fx  * fy;
        sWt[tid] = w;
    }
    __syncthreads();

    int g  = tid >> 6;        // cell-group within chunk 0..3
    int ch = tid & 63;        // float4 channel index 0..63

    float* obase = out + (size_t)roi * NCELL * FM_C;

    const int NCHUNK = (NCELL + DEPTH - 1) / DEPTH;   // 13
    for (int chunk = 0; chunk < NCHUNK; chunk++) {
        int base = chunk * DEPTH;
        int cnt  = min(DEPTH, NCELL - base);

        // Producer: arm + issue 4 bulk 1KB gathers per cell of this chunk.
        if (tid == 0) {
            for (int k = 0; k < cnt; k++) {
                uint32_t mb = s2u(&mbar[k]);
                mbar_expect_tx(mb, 4 * FM_C * 4);
                int4 idx = sIdx[base + k];
                uint32_t dst = s2u(&bufs[k][0]);
                bulk_ld(dst,                 fm + idx.x, FM_C * 4, mb);
                bulk_ld(dst + 1 * FM_C * 4,  fm + idx.y, FM_C * 4, mb);
                bulk_ld(dst + 2 * FM_C * 4,  fm + idx.z, FM_C * 4, mb);
                bulk_ld(dst + 3 * FM_C * 4,  fm + idx.w, FM_C * 4, mb);
            }
        }

        // Consumer: each 64-thread group handles one cell.
        if (g < cnt) {
            mbar_wait(s2u(&mbar[g]), chunk & 1);

            float4 w = sWt[base + g];
            const float4* b = (const float4*)&bufs[g][0];
            float4 g00 = b[0 * 64 + ch];
            float4 g01 = b[1 * 64 + ch];
            float4 g10 = b[2 * 64 + ch];
            float4 g11 = b[3 * 64 + ch];

            float4 r;
            r.x = g00.x * w.x + g01.x * w.y + g10.x * w.z + g11.x * w.w;
            r.y = g00.y * w.x + g01.y * w.y + g10.y * w.z + g11.y * w.w;
            r.z = g00.z * w.x + g01.z * w.y + g10.z * w.z + g11.z * w.w;
            r.w = g00.w * w.x + g01.w * w.y + g10.w * w.z + g11.w * w.w;

            __stcs((float4*)(obase + (base + g) * FM_C) + ch, r);
        }
        __syncthreads();   // buffers reusable next chunk
    }
}

extern "C" void kernel_launch(void* const* d_in, const int* in_sizes, int n_in,
                              void* d_out, int out_size)
{
    const float* fm  = (const float*)d_in[0];
    const int* rois  = (const int*)d_in[1];
    float* out       = (float*)d_out;

    int n_rois = in_sizes[1] / 5;

    roi_pool_kernel<<<n_rois, 256>>>(fm, rois, out);
}